// round 16
// baseline (speedup 1.0000x reference)
#include <cuda_runtime.h>
#include <cuda_fp16.h>
#include <cstdint>
#include <cstddef>

#define BB   2
#define LL   2048
#define DIMM 2048
#define HH   16
#define DD   128
#define E3   6144
#define MROWS (BB*LL)
#define BH   (BB*HH)

// ---- GEMM tiling (2-stage, BK=32) ----
#define BM 128
#define BN 128
#define SKP 40
#define STG_E (128 * SKP)
#define STG_B (STG_E * 2)               // 10240 B
#define SMEM_STAGE (3 * STG_B)
#define SMEM_TOTAL (2 * SMEM_STAGE)     // 61440 B (proj)
#define SMEM_STAGE1 (2 * STG_B)
#define SMEM_TOTAL1 (2 * SMEM_STAGE1)   // 40960 B (QKV)

// ---- flash tiling: KV chunk = 32, 2 CTAs/SM ----
#define QBYTES (128 * 136 * 2)
#define KVB    (32 * 136 * 2)
#define SM_S0  QBYTES
#define FSTAGE (4 * KVB)
#define FSMEM  (SM_S0 + 2 * FSTAGE)     // 104448

#define N4_X  (MROWS * DIMM / 4)
#define N4_WQ (E3 * DIMM / 4)
#define N4_WP (DIMM * DIMM / 4)

// ---------------------------------------------------------------------------
// Scratch
// ---------------------------------------------------------------------------
__device__ float g_qkv[(size_t)MROWS * E3];
__device__ __half g_xh [(size_t)MROWS * DIMM];
__device__ __half g_wqh[(size_t)E3 * DIMM];
__device__ __half g_wph[(size_t)DIMM * DIMM], g_wpl[(size_t)DIMM * DIMM];
__device__ __half g_qh [(size_t)BH * LL * DD];
__device__ __half g_kh [(size_t)BH * LL * DD], g_kl[(size_t)BH * LL * DD];
__device__ __half g_vh [(size_t)BH * LL * DD], g_vl[(size_t)BH * LL * DD];
__device__ __half g_oh [(size_t)MROWS * DIMM];

// ---------------------------------------------------------------------------
// PTX helpers
// ---------------------------------------------------------------------------
__device__ __forceinline__ uint32_t smem_u32(const void* p) {
    uint32_t a;
    asm("{ .reg .u64 t; cvta.to.shared.u64 t, %1; cvt.u32.u64 %0, t; }" : "=r"(a) : "l"(p));
    return a;
}

#define CP16(dst, src) \
    asm volatile("cp.async.cg.shared.global [%0], [%1], 16;" :: "r"(dst), "l"(src))
#define CP_COMMIT() asm volatile("cp.async.commit_group;" ::: "memory")
#define CP_WAIT(n)  asm volatile("cp.async.wait_group %0;" :: "n"(n) : "memory")

#define LDSM_X4(r, addr) \
    asm volatile("ldmatrix.sync.aligned.m8n8.x4.shared.b16 {%0,%1,%2,%3}, [%4];" \
        : "=r"((r)[0]), "=r"((r)[1]), "=r"((r)[2]), "=r"((r)[3]) : "r"(addr))
#define LDSM_X4T(r, addr) \
    asm volatile("ldmatrix.sync.aligned.m8n8.x4.trans.shared.b16 {%0,%1,%2,%3}, [%4];" \
        : "=r"((r)[0]), "=r"((r)[1]), "=r"((r)[2]), "=r"((r)[3]) : "r"(addr))

__device__ __forceinline__ void mma_f16(float* d, const uint32_t* a, const uint32_t* b) {
    asm volatile(
        "mma.sync.aligned.m16n8k16.row.col.f32.f16.f16.f32 "
        "{%0,%1,%2,%3}, {%4,%5,%6,%7}, {%8,%9}, {%0,%1,%2,%3};"
        : "+f"(d[0]), "+f"(d[1]), "+f"(d[2]), "+f"(d[3])
        : "r"(a[0]), "r"(a[1]), "r"(a[2]), "r"(a[3]), "r"(b[0]), "r"(b[1]));
}

__device__ __forceinline__ void cvt2h(float x, float y, uint32_t& h) {
    __half2 t = __floats2half2_rn(x, y);
    h = *(uint32_t*)&t;
}
__device__ __forceinline__ void split2h(float x, float y, uint32_t& hi, uint32_t& lo) {
    __half2 h = __floats2half2_rn(x, y);
    __half2 l = __floats2half2_rn(x - __half2float(__low2half(h)),
                                  y - __half2float(__high2half(h)));
    hi = *(uint32_t*)&h;
    lo = *(uint32_t*)&l;
}

// ---------------------------------------------------------------------------
// Fused converter
// ---------------------------------------------------------------------------
__global__ __launch_bounds__(256) void convert_all(
    const float* __restrict__ x, const float* __restrict__ wq,
    const float* __restrict__ wp)
{
    int i = blockIdx.x * blockDim.x + threadIdx.x;
    if (i < N4_X) {
        float4 f = *(const float4*)(x + (size_t)i * 4);
        uint2 hv;
        cvt2h(f.x, f.y, hv.x); cvt2h(f.z, f.w, hv.y);
        *(uint2*)(g_xh + (size_t)i * 4) = hv;
    } else if (i < N4_X + N4_WQ) {
        int j = i - N4_X;
        float4 f = *(const float4*)(wq + (size_t)j * 4);
        uint2 hv;
        cvt2h(f.x, f.y, hv.x); cvt2h(f.z, f.w, hv.y);
        *(uint2*)(g_wqh + (size_t)j * 4) = hv;
    } else {
        int j = i - N4_X - N4_WQ;
        if (j >= N4_WP) return;
        float4 f = *(const float4*)(wp + (size_t)j * 4);
        uint2 hv, lv;
        split2h(f.x, f.y, hv.x, lv.x);
        split2h(f.z, f.w, hv.y, lv.y);
        *(uint2*)(g_wph + (size_t)j * 4) = hv;
        *(uint2*)(g_wpl + (size_t)j * 4) = lv;
    }
}

// ---------------------------------------------------------------------------
// 1-MMA GEMM (NT): C = A_h @ B_h^T   (QKV) — B loads as ks-merged X4
// ---------------------------------------------------------------------------
__global__ __launch_bounds__(256) void gemm_tc1(
    const __half* __restrict__ Ahg, const __half* __restrict__ Bhg,
    float* __restrict__ C, int K, int lda, int ldb, int ldc)
{
    extern __shared__ __half sm[];
    const uint32_t smb = smem_u32(sm);
    const int tid  = threadIdx.x;
    const int lane = tid & 31;
    const int wrp  = tid >> 5;
    const int wy   = wrp >> 2;
    const int wx   = wrp & 3;

    const int m0 = blockIdx.y * BM;
    const int n0 = blockIdx.x * BN;

    float acc[4][4][4];
#pragma unroll
    for (int m = 0; m < 4; m++)
#pragma unroll
        for (int n = 0; n < 4; n++)
#pragma unroll
            for (int i = 0; i < 4; i++) acc[m][n][i] = 0.f;

    const int nchunks = K >> 5;
    const int ar = tid >> 1;
    const int ak = (tid & 1) * 16;

    auto issue = [&](int c) {
        const int s = c & 1;
        const int k0 = c << 5;
        const uint32_t sb = smb + s * SMEM_STAGE1;
        const uint32_t aoff = (uint32_t)(ar * SKP + ak) * 2u;
        CP16(sb + aoff,              Ahg + (long long)(m0 + ar) * lda + k0 + ak);
        CP16(sb + aoff + 16,         Ahg + (long long)(m0 + ar) * lda + k0 + ak + 8);
        CP16(sb + STG_B + aoff,      Bhg + (long long)(n0 + ar) * ldb + k0 + ak);
        CP16(sb + STG_B + aoff + 16, Bhg + (long long)(n0 + ar) * ldb + k0 + ak + 8);
        CP_COMMIT();
    };

    issue(0);

    // B X4: lanes 0-7 -> ks0 k[0:8), 8-15 -> ks0 k[8:16), 16-23 -> ks1 k[16:24), 24-31 -> ks1 k[24:32)
    const uint32_t bcol = (uint32_t)(lane >> 3) * 8u;

    for (int c = 0; c < nchunks; c++) {
        CP_WAIT(0);
        __syncthreads();
        if (c + 1 < nchunks) issue(c + 1);

        const uint32_t sb = smb + (c & 1) * SMEM_STAGE1;
        const uint32_t AhB = sb, BhB = sb + STG_B;

        uint32_t bHf[4][4];
#pragma unroll
        for (int n = 0; n < 4; n++) {
            const uint32_t off =
                (uint32_t)((wx * 32 + n * 8 + (lane & 7)) * SKP) * 2u + bcol * 2u;
            LDSM_X4(bHf[n], BhB + off);
        }

#pragma unroll
        for (int ks = 0; ks < 2; ks++) {
            uint32_t aH[4][4];
            const int kc = ks * 16 + (lane >> 4) * 8;
#pragma unroll
            for (int m = 0; m < 4; m++) {
                const uint32_t off =
                    (uint32_t)((wy * 64 + m * 16 + (lane & 15)) * SKP + kc) * 2u;
                LDSM_X4(aH[m], AhB + off);
            }
#pragma unroll
            for (int m = 0; m < 4; m++)
#pragma unroll
                for (int n = 0; n < 4; n++)
                    mma_f16(acc[m][n], aH[m], bHf[n] + ks * 2);
        }
    }

#pragma unroll
    for (int m = 0; m < 4; m++) {
        const int row = m0 + wy * 64 + m * 16 + (lane >> 2);
#pragma unroll
        for (int n = 0; n < 4; n++) {
            const int col = n0 + wx * 32 + n * 8 + (lane & 3) * 2;
            float2 v0, v1;
            v0.x = acc[m][n][0]; v0.y = acc[m][n][1];
            v1.x = acc[m][n][2]; v1.y = acc[m][n][3];
            *(float2*)(C + (long long)row * ldc + col)       = v0;
            *(float2*)(C + (long long)(row + 8) * ldc + col) = v1;
        }
    }
}

// ---------------------------------------------------------------------------
// 2-MMA GEMM (NT): C = A_h @ (B_h + B_l)^T (+bias)   (proj) — ks-merged X4 B
// ---------------------------------------------------------------------------
__global__ __launch_bounds__(256) void gemm_tc(
    const __half* __restrict__ Ahg,
    const __half* __restrict__ Bhg, const __half* __restrict__ Blg,
    float* __restrict__ C, const float* __restrict__ bias,
    int K, int lda, int ldb, int ldc)
{
    extern __shared__ __half sm[];
    const uint32_t smb = smem_u32(sm);
    const int tid  = threadIdx.x;
    const int lane = tid & 31;
    const int wrp  = tid >> 5;
    const int wy   = wrp >> 2;
    const int wx   = wrp & 3;

    const int m0 = blockIdx.y * BM;
    const int n0 = blockIdx.x * BN;

    float acc[4][4][4];
#pragma unroll
    for (int m = 0; m < 4; m++)
#pragma unroll
        for (int n = 0; n < 4; n++)
#pragma unroll
            for (int i = 0; i < 4; i++) acc[m][n][i] = 0.f;

    const int nchunks = K >> 5;
    const int ar = tid >> 1;
    const int ak = (tid & 1) * 16;

    auto issue = [&](int c) {
        const int s = c & 1;
        const int k0 = c << 5;
        const uint32_t sb = smb + s * SMEM_STAGE;
        const uint32_t aoff = (uint32_t)(ar * SKP + ak) * 2u;
        CP16(sb + aoff,                  Ahg + (long long)(m0 + ar) * lda + k0 + ak);
        CP16(sb + aoff + 16,             Ahg + (long long)(m0 + ar) * lda + k0 + ak + 8);
        CP16(sb + STG_B + aoff,          Bhg + (long long)(n0 + ar) * ldb + k0 + ak);
        CP16(sb + STG_B + aoff + 16,     Bhg + (long long)(n0 + ar) * ldb + k0 + ak + 8);
        CP16(sb + 2 * STG_B + aoff,      Blg + (long long)(n0 + ar) * ldb + k0 + ak);
        CP16(sb + 2 * STG_B + aoff + 16, Blg + (long long)(n0 + ar) * ldb + k0 + ak + 8);
        CP_COMMIT();
    };

    issue(0);

    const uint32_t bcol = (uint32_t)(lane >> 3) * 8u;

    for (int c = 0; c < nchunks; c++) {
        CP_WAIT(0);
        __syncthreads();
        if (c + 1 < nchunks) issue(c + 1);

        const uint32_t sb = smb + (c & 1) * SMEM_STAGE;
        const uint32_t AhB = sb;
        const uint32_t BhB = sb + STG_B, BlB = sb + 2 * STG_B;

        uint32_t bHf[4][4], bLf[4][4];
#pragma unroll
        for (int n = 0; n < 4; n++) {
            const uint32_t off =
                (uint32_t)((wx * 32 + n * 8 + (lane & 7)) * SKP) * 2u + bcol * 2u;
            LDSM_X4(bHf[n], BhB + off);
            LDSM_X4(bLf[n], BlB + off);
        }

#pragma unroll
        for (int ks = 0; ks < 2; ks++) {
            uint32_t aH[4][4];
            const int kc = ks * 16 + (lane >> 4) * 8;
#pragma unroll
            for (int m = 0; m < 4; m++) {
                const uint32_t off =
                    (uint32_t)((wy * 64 + m * 16 + (lane & 15)) * SKP + kc) * 2u;
                LDSM_X4(aH[m], AhB + off);
            }
#pragma unroll
            for (int m = 0; m < 4; m++)
#pragma unroll
                for (int n = 0; n < 4; n++) {
                    mma_f16(acc[m][n], aH[m], bHf[n] + ks * 2);
                    mma_f16(acc[m][n], aH[m], bLf[n] + ks * 2);
                }
        }
    }

#pragma unroll
    for (int m = 0; m < 4; m++) {
        const int row = m0 + wy * 64 + m * 16 + (lane >> 2);
#pragma unroll
        for (int n = 0; n < 4; n++) {
            const int col = n0 + wx * 32 + n * 8 + (lane & 3) * 2;
            float2 v0, v1;
            v0.x = acc[m][n][0]; v0.y = acc[m][n][1];
            v1.x = acc[m][n][2]; v1.y = acc[m][n][3];
            if (bias) {
                float2 bb = *(const float2*)(bias + col);
                v0.x += bb.x; v0.y += bb.y;
                v1.x += bb.x; v1.y += bb.y;
            }
            *(float2*)(C + (long long)row * ldc + col)       = v0;
            *(float2*)(C + (long long)(row + 8) * ldc + col) = v1;
        }
    }
}

// ---------------------------------------------------------------------------
// Fused flash attention: KV chunk 32, 2 CTAs/SM — K loads kd-pair-merged X4
// ---------------------------------------------------------------------------
__global__ __launch_bounds__(256, 2) void flash_attn()
{
    extern __shared__ char smc[];
    const uint32_t smb = smem_u32(smc);
    const int tid = threadIdx.x, lane = tid & 31, w = tid >> 5;
    const int m0 = blockIdx.x * 128;
    const int bh = blockIdx.y;
    const long long hb = (long long)bh * LL * DD;
    const __half *qhp = g_qh + hb;
    const __half *khp = g_kh + hb, *klp = g_kl + hb;
    const __half *vhp = g_vh + hb, *vlp = g_vl + hb;

#pragma unroll
    for (int i = 0; i < 8; i++) {
        int idx = tid + i * 256;
        int row = idx >> 4, seg = idx & 15;
        CP16(smb + (uint32_t)row * 272u + seg * 16,
             qhp + (long long)(m0 + row) * DD + seg * 8);
    }
    auto stage_kv = [&](int c) {
        const uint32_t base = smb + SM_S0 + (uint32_t)(c & 1) * FSTAGE;
#pragma unroll
        for (int i = 0; i < 8; i++) {
            int idx = tid + i * 256;
            int mat = (idx >> 9) & 3, row = (idx >> 4) & 31, seg = idx & 15;
            const __half* sp = (mat == 0) ? khp : (mat == 1) ? klp
                             : (mat == 2) ? vhp : vlp;
            CP16(base + (uint32_t)mat * KVB + (uint32_t)row * 272u + seg * 16,
                 sp + (long long)(c * 32 + row) * DD + seg * 8);
        }
        CP_COMMIT();
    };
    stage_kv(0);

    float Oacc[16][4];
#pragma unroll
    for (int n = 0; n < 16; n++)
#pragma unroll
        for (int i = 0; i < 4; i++) Oacc[n][i] = 0.f;
    float mr0 = -1e30f, mr1 = -1e30f, lr0 = 0.f, lr1 = 0.f;

    const uint32_t bg8 = (uint32_t)(lane >> 3) * 8u;   // X4 k-column selector

    for (int c = 0; c < 64; c++) {
        CP_WAIT(0);
        __syncthreads();
        if (c + 1 < 64) stage_kv(c + 1);

        const uint32_t stg = smb + SM_S0 + (uint32_t)(c & 1) * FSTAGE;
        const uint32_t Kh = stg, Kl = stg + KVB, Vh = stg + 2 * KVB, Vl = stg + 3 * KVB;

        float sacc[4][4];
#pragma unroll
        for (int n = 0; n < 4; n++)
#pragma unroll
            for (int i = 0; i < 4; i++) sacc[n][i] = 0.f;

        // ---- S = Q @ K^T: kd pairs merged into X4 K loads ----
#pragma unroll
        for (int kdp = 0; kdp < 4; kdp++) {
            uint32_t qf0[4], qf1[4];
            const uint32_t q0off =
                ((uint32_t)(w * 16 + (lane & 15)) * 136u + (2 * kdp) * 16 + (lane >> 4) * 8) * 2u;
            const uint32_t q1off =
                ((uint32_t)(w * 16 + (lane & 15)) * 136u + (2 * kdp + 1) * 16 + (lane >> 4) * 8) * 2u;
            LDSM_X4(qf0, smb + q0off);
            LDSM_X4(qf1, smb + q1off);

            uint32_t bh4[4][4], bl4[4][4];
            const uint32_t kcol = (uint32_t)(kdp * 32) + bg8;
#pragma unroll
            for (int nf = 0; nf < 4; nf++) {
                const uint32_t off = ((uint32_t)(nf * 8 + (lane & 7)) * 136u + kcol) * 2u;
                LDSM_X4(bh4[nf], Kh + off);
                LDSM_X4(bl4[nf], Kl + off);
            }
#pragma unroll
            for (int nf = 0; nf < 4; nf++) {
                mma_f16(sacc[nf], qf0, bh4[nf]);
                mma_f16(sacc[nf], qf0, bl4[nf]);
            }
#pragma unroll
            for (int nf = 0; nf < 4; nf++) {
                mma_f16(sacc[nf], qf1, bh4[nf] + 2);
                mma_f16(sacc[nf], qf1, bl4[nf] + 2);
            }
        }

        // ---- online softmax ----
        float cm0 = -1e30f, cm1 = -1e30f;
#pragma unroll
        for (int nf = 0; nf < 4; nf++) {
            cm0 = fmaxf(cm0, fmaxf(sacc[nf][0], sacc[nf][1]));
            cm1 = fmaxf(cm1, fmaxf(sacc[nf][2], sacc[nf][3]));
        }
        cm0 = fmaxf(cm0, __shfl_xor_sync(0xffffffffu, cm0, 1));
        cm0 = fmaxf(cm0, __shfl_xor_sync(0xffffffffu, cm0, 2));
        cm1 = fmaxf(cm1, __shfl_xor_sync(0xffffffffu, cm1, 1));
        cm1 = fmaxf(cm1, __shfl_xor_sync(0xffffffffu, cm1, 2));
        const float mn0 = fmaxf(mr0, cm0), mn1 = fmaxf(mr1, cm1);
        const float a0 = __expf(mr0 - mn0), a1 = __expf(mr1 - mn1);
        mr0 = mn0; mr1 = mn1;

        float s0 = 0.f, s1 = 0.f;
#pragma unroll
        for (int nf = 0; nf < 4; nf++) {
            sacc[nf][0] = __expf(sacc[nf][0] - mn0);
            sacc[nf][1] = __expf(sacc[nf][1] - mn0);
            sacc[nf][2] = __expf(sacc[nf][2] - mn1);
            sacc[nf][3] = __expf(sacc[nf][3] - mn1);
            s0 += sacc[nf][0] + sacc[nf][1];
            s1 += sacc[nf][2] + sacc[nf][3];
        }
        s0 += __shfl_xor_sync(0xffffffffu, s0, 1);
        s0 += __shfl_xor_sync(0xffffffffu, s0, 2);
        s1 += __shfl_xor_sync(0xffffffffu, s1, 1);
        s1 += __shfl_xor_sync(0xffffffffu, s1, 2);
        lr0 = lr0 * a0 + s0;
        lr1 = lr1 * a1 + s1;

#pragma unroll
        for (int n = 0; n < 16; n++) {
            Oacc[n][0] *= a0; Oacc[n][1] *= a0;
            Oacc[n][2] *= a1; Oacc[n][3] *= a1;
        }

        uint32_t ph[2][4];
#pragma unroll
        for (int kv = 0; kv < 2; kv++) {
            cvt2h(sacc[2 * kv][0],     sacc[2 * kv][1],     ph[kv][0]);
            cvt2h(sacc[2 * kv][2],     sacc[2 * kv][3],     ph[kv][1]);
            cvt2h(sacc[2 * kv + 1][0], sacc[2 * kv + 1][1], ph[kv][2]);
            cvt2h(sacc[2 * kv + 1][2], sacc[2 * kv + 1][3], ph[kv][3]);
        }

#pragma unroll
        for (int kv = 0; kv < 2; kv++) {
            const uint32_t vrow = (uint32_t)(kv * 16 + (lane & 15));
#pragma unroll
            for (int nfp = 0; nfp < 8; nfp++) {
                const uint32_t voff =
                    (vrow * 136u + (uint32_t)(nfp * 16 + ((lane >> 4) & 1) * 8)) * 2u;
                uint32_t vbh[4], vbl[4];
                LDSM_X4T(vbh, Vh + voff);
                LDSM_X4T(vbl, Vl + voff);
                mma_f16(Oacc[2 * nfp],     ph[kv], vbh);
                mma_f16(Oacc[2 * nfp],     ph[kv], vbl);
                mma_f16(Oacc[2 * nfp + 1], ph[kv], vbh + 2);
                mma_f16(Oacc[2 * nfp + 1], ph[kv], vbl + 2);
            }
        }
    }

    const float inv0 = 1.f / lr0, inv1 = 1.f / lr1;
    const int b = bh >> 4, h = bh & 15;
    const int r0 = m0 + w * 16 + (lane >> 2);
    const long long base0 = (long long)(b * LL + r0) * DIMM + h * DD;
    const long long base1 = base0 + 8LL * DIMM;
#pragma unroll
    for (int nf = 0; nf < 16; nf++) {
        const int col = nf * 8 + (lane & 3) * 2;
        uint32_t hh;
        cvt2h(Oacc[nf][0] * inv0, Oacc[nf][1] * inv0, hh);
        *(uint32_t*)(g_oh + base0 + col) = hh;
        cvt2h(Oacc[nf][2] * inv1, Oacc[nf][3] * inv1, hh);
        *(uint32_t*)(g_oh + base1 + col) = hh;
    }
}

// ---------------------------------------------------------------------------
// Prep: RMSNorm + RoPE (+attn scale on q) -> fp16 q(hi), k(hi/lo), v(hi/lo)
// ---------------------------------------------------------------------------
__global__ __launch_bounds__(256) void prep_kernel(
    const float* __restrict__ qkv, const float* __restrict__ pe,
    const float* __restrict__ qsc, const float* __restrict__ ksc)
{
    const int warp = (blockIdx.x * blockDim.x + threadIdx.x) >> 5;
    const int lane = threadIdx.x & 31;
    const int b = warp >> 15;
    const int rem = warp & 32767;
    const int h = rem >> 11;
    const int l = rem & 2047;

    const long long src = ((long long)(b * LL + l)) * E3 + h * DD + lane * 4;
    float4 qv = *(const float4*)(qkv + src);
    float4 kv = *(const float4*)(qkv + src + DIMM);
    float4 vv = *(const float4*)(qkv + src + 2 * DIMM);

    float sq = qv.x * qv.x + qv.y * qv.y + qv.z * qv.z + qv.w * qv.w;
#pragma unroll
    for (int o = 16; o; o >>= 1) sq += __shfl_xor_sync(0xffffffffu, sq, o);
    float rq = rsqrtf(sq * (1.0f / 128.0f) + 1e-6f);
    float4 qs4 = *(const float4*)(qsc + lane * 4);
    qv.x *= rq * qs4.x; qv.y *= rq * qs4.y; qv.z *= rq * qs4.z; qv.w *= rq * qs4.w;

    float sk = kv.x * kv.x + kv.y * kv.y + kv.z * kv.z + kv.w * kv.w;
#pragma unroll
    for (int o = 16; o; o >>= 1) sk += __shfl_xor_sync(0xffffffffu, sk, o);
    float rk = rsqrtf(sk * (1.0f / 128.0f) + 1e-6f);
    float4 ks4 = *(const float4*)(ksc + lane * 4);
    kv.x *= rk * ks4.x; kv.y *= rk * ks4.y; kv.z *= rk * ks4.z; kv.w *= rk * ks4.w;

    const float* peb = pe + (long long)l * 256 + lane * 8;
    float a00 = peb[0], a01 = peb[1], a10 = peb[2], a11 = peb[3];
    float b00 = peb[4], b01 = peb[5], b10 = peb[6], b11 = peb[7];

    const float asc = 0.08838834764831845f;
    float4 qo, ko;
    qo.x = (a00 * qv.x + a01 * qv.y) * asc;  qo.y = (a10 * qv.x + a11 * qv.y) * asc;
    qo.z = (b00 * qv.z + b01 * qv.w) * asc;  qo.w = (b10 * qv.z + b11 * qv.w) * asc;
    ko.x = a00 * kv.x + a01 * kv.y;  ko.y = a10 * kv.x + a11 * kv.y;
    ko.z = b00 * kv.z + b01 * kv.w;  ko.w = b10 * kv.z + b11 * kv.w;

    const long long dst = (long long)warp * DD + lane * 4;
    uint2 hv, lv;
    cvt2h(qo.x, qo.y, hv.x); cvt2h(qo.z, qo.w, hv.y);
    *(uint2*)(g_qh + dst) = hv;
    split2h(ko.x, ko.y, hv.x, lv.x); split2h(ko.z, ko.w, hv.y, lv.y);
    *(uint2*)(g_kh + dst) = hv; *(uint2*)(g_kl + dst) = lv;
    split2h(vv.x, vv.y, hv.x, lv.x); split2h(vv.z, vv.w, hv.y, lv.y);
    *(uint2*)(g_vh + dst) = hv; *(uint2*)(g_vl + dst) = lv;
}

// ---------------------------------------------------------------------------
// Launch
// ---------------------------------------------------------------------------
extern "C" void kernel_launch(void* const* d_in, const int* in_sizes, int n_in,
                              void* d_out, int out_size)
{
    const float* x      = (const float*)d_in[0];
    const float* pe     = (const float*)d_in[1];
    const float* qkv_w  = (const float*)d_in[2];
    const float* q_sc   = (const float*)d_in[3];
    const float* k_sc   = (const float*)d_in[4];
    const float* proj_w = (const float*)d_in[5];
    const float* proj_b = (const float*)d_in[6];
    float* out = (float*)d_out;

    float* qkv;
    __half *xh, *wqh, *wph, *wpl, *oh;
    cudaGetSymbolAddress((void**)&qkv, g_qkv);
    cudaGetSymbolAddress((void**)&xh,  g_xh);
    cudaGetSymbolAddress((void**)&wqh, g_wqh);
    cudaGetSymbolAddress((void**)&wph, g_wph); cudaGetSymbolAddress((void**)&wpl, g_wpl);
    cudaGetSymbolAddress((void**)&oh,  g_oh);

    cudaFuncSetAttribute(gemm_tc1, cudaFuncAttributeMaxDynamicSharedMemorySize, SMEM_TOTAL1);
    cudaFuncSetAttribute(gemm_tc, cudaFuncAttributeMaxDynamicSharedMemorySize, SMEM_TOTAL);
    cudaFuncSetAttribute(flash_attn, cudaFuncAttributeMaxDynamicSharedMemorySize, FSMEM);

    convert_all<<<(N4_X + N4_WQ + N4_WP + 255) / 256, 256>>>(x, qkv_w, proj_w);

    gemm_tc1<<<dim3(E3 / BN, MROWS / BM, 1), 256, SMEM_TOTAL1>>>(
        xh, wqh, qkv, DIMM, DIMM, DIMM, E3);

    prep_kernel<<<(BH * LL) / 8, 256>>>(qkv, pe, q_sc, k_sc);

    flash_attn<<<dim3(LL / 128, BH, 1), 256, FSMEM>>>();

    gemm_tc<<<dim3(DIMM / BN, MROWS / BM, 1), 256, SMEM_TOTAL>>>(
        oh, wph, wpl, out, proj_b, DIMM, DIMM, DIMM, DIMM);
}

// round 17
// speedup vs baseline: 1.0437x; 1.0437x over previous
#include <cuda_runtime.h>
#include <cuda_fp16.h>
#include <cstdint>
#include <cstddef>

#define BB   2
#define LL   2048
#define DIMM 2048
#define HH   16
#define DD   128
#define E3   6144
#define MROWS (BB*LL)
#define BH   (BB*HH)

// ---- GEMM tiling (2-stage, BK=32) ----
#define BM 128
#define BN 128
#define SKP 40
#define STG_E (128 * SKP)
#define STG_B (STG_E * 2)               // 10240 B
#define SMEM_STAGE (3 * STG_B)
#define SMEM_TOTAL (2 * SMEM_STAGE)     // 61440 B (proj, 2-MMA)
#define SMEM_STAGE1 (2 * STG_B)
#define SMEM_TOTAL1 (2 * SMEM_STAGE1)   // 40960 B (QKV, 1-MMA)

// ---- flash tiling: KV chunk = 32, 2 CTAs/SM ----
#define QBYTES (128 * 136 * 2)
#define KVB    (32 * 136 * 2)
#define SM_S0  QBYTES
#define FSTAGE (4 * KVB)
#define FSMEM  (SM_S0 + 2 * FSTAGE)     // 104448

// convert sizing (n4 units of float4)
#define N4_X  (MROWS * DIMM / 4)
#define N4_WQ (E3 * DIMM / 4)
#define N4_WP (DIMM * DIMM / 4)

// ---------------------------------------------------------------------------
// Scratch
// ---------------------------------------------------------------------------
__device__ float g_qkv[(size_t)MROWS * E3];
__device__ __half g_xh [(size_t)MROWS * DIMM];
__device__ __half g_wqh[(size_t)E3 * DIMM];
__device__ __half g_wph[(size_t)DIMM * DIMM], g_wpl[(size_t)DIMM * DIMM];
__device__ __half g_qh [(size_t)BH * LL * DD];
__device__ __half g_kh [(size_t)BH * LL * DD], g_kl[(size_t)BH * LL * DD];
__device__ __half g_vh [(size_t)BH * LL * DD], g_vl[(size_t)BH * LL * DD];
__device__ __half g_oh [(size_t)MROWS * DIMM];

// ---------------------------------------------------------------------------
// PTX helpers
// ---------------------------------------------------------------------------
__device__ __forceinline__ uint32_t smem_u32(const void* p) {
    uint32_t a;
    asm("{ .reg .u64 t; cvta.to.shared.u64 t, %1; cvt.u32.u64 %0, t; }" : "=r"(a) : "l"(p));
    return a;
}

#define CP16(dst, src) \
    asm volatile("cp.async.cg.shared.global [%0], [%1], 16;" :: "r"(dst), "l"(src))
#define CP_COMMIT() asm volatile("cp.async.commit_group;" ::: "memory")
#define CP_WAIT(n)  asm volatile("cp.async.wait_group %0;" :: "n"(n) : "memory")

#define LDSM_X4(r, addr) \
    asm volatile("ldmatrix.sync.aligned.m8n8.x4.shared.b16 {%0,%1,%2,%3}, [%4];" \
        : "=r"((r)[0]), "=r"((r)[1]), "=r"((r)[2]), "=r"((r)[3]) : "r"(addr))
#define LDSM_X2(r, addr) \
    asm volatile("ldmatrix.sync.aligned.m8n8.x2.shared.b16 {%0,%1}, [%2];" \
        : "=r"((r)[0]), "=r"((r)[1]) : "r"(addr))
#define LDSM_X4T(r, addr) \
    asm volatile("ldmatrix.sync.aligned.m8n8.x4.trans.shared.b16 {%0,%1,%2,%3}, [%4];" \
        : "=r"((r)[0]), "=r"((r)[1]), "=r"((r)[2]), "=r"((r)[3]) : "r"(addr))

__device__ __forceinline__ void mma_f16(float* d, const uint32_t* a, const uint32_t* b) {
    asm volatile(
        "mma.sync.aligned.m16n8k16.row.col.f32.f16.f16.f32 "
        "{%0,%1,%2,%3}, {%4,%5,%6,%7}, {%8,%9}, {%0,%1,%2,%3};"
        : "+f"(d[0]), "+f"(d[1]), "+f"(d[2]), "+f"(d[3])
        : "r"(a[0]), "r"(a[1]), "r"(a[2]), "r"(a[3]), "r"(b[0]), "r"(b[1]));
}

__device__ __forceinline__ void cvt2h(float x, float y, uint32_t& h) {
    __half2 t = __floats2half2_rn(x, y);
    h = *(uint32_t*)&t;
}
__device__ __forceinline__ void split2h(float x, float y, uint32_t& hi, uint32_t& lo) {
    __half2 h = __floats2half2_rn(x, y);
    __half2 l = __floats2half2_rn(x - __half2float(__low2half(h)),
                                  y - __half2float(__high2half(h)));
    hi = *(uint32_t*)&h;
    lo = *(uint32_t*)&l;
}

// ---------------------------------------------------------------------------
// Fused converter: x -> hi, qkv_w -> hi, proj_w -> hi/lo, one launch.
// ---------------------------------------------------------------------------
__global__ __launch_bounds__(256) void convert_all(
    const float* __restrict__ x, const float* __restrict__ wq,
    const float* __restrict__ wp)
{
    int i = blockIdx.x * blockDim.x + threadIdx.x;
    if (i < N4_X) {
        float4 f = *(const float4*)(x + (size_t)i * 4);
        uint2 hv;
        cvt2h(f.x, f.y, hv.x); cvt2h(f.z, f.w, hv.y);
        *(uint2*)(g_xh + (size_t)i * 4) = hv;
    } else if (i < N4_X + N4_WQ) {
        int j = i - N4_X;
        float4 f = *(const float4*)(wq + (size_t)j * 4);
        uint2 hv;
        cvt2h(f.x, f.y, hv.x); cvt2h(f.z, f.w, hv.y);
        *(uint2*)(g_wqh + (size_t)j * 4) = hv;
    } else {
        int j = i - N4_X - N4_WQ;
        if (j >= N4_WP) return;
        float4 f = *(const float4*)(wp + (size_t)j * 4);
        uint2 hv, lv;
        split2h(f.x, f.y, hv.x, lv.x);
        split2h(f.z, f.w, hv.y, lv.y);
        *(uint2*)(g_wph + (size_t)j * 4) = hv;
        *(uint2*)(g_wpl + (size_t)j * 4) = lv;
    }
}

// ---------------------------------------------------------------------------
// 1-MMA GEMM (NT): C = A_h @ B_h^T   (QKV)
// ---------------------------------------------------------------------------
__global__ __launch_bounds__(256) void gemm_tc1(
    const __half* __restrict__ Ahg, const __half* __restrict__ Bhg,
    float* __restrict__ C, int K, int lda, int ldb, int ldc)
{
    extern __shared__ __half sm[];
    const uint32_t smb = smem_u32(sm);
    const int tid  = threadIdx.x;
    const int lane = tid & 31;
    const int wrp  = tid >> 5;
    const int wy   = wrp >> 2;
    const int wx   = wrp & 3;

    const int m0 = blockIdx.y * BM;
    const int n0 = blockIdx.x * BN;

    float acc[4][4][4];
#pragma unroll
    for (int m = 0; m < 4; m++)
#pragma unroll
        for (int n = 0; n < 4; n++)
#pragma unroll
            for (int i = 0; i < 4; i++) acc[m][n][i] = 0.f;

    const int nchunks = K >> 5;
    const int ar = tid >> 1;
    const int ak = (tid & 1) * 16;

    auto issue = [&](int c) {
        const int s = c & 1;
        const int k0 = c << 5;
        const uint32_t sb = smb + s * SMEM_STAGE1;
        const uint32_t aoff = (uint32_t)(ar * SKP + ak) * 2u;
        CP16(sb + aoff,              Ahg + (long long)(m0 + ar) * lda + k0 + ak);
        CP16(sb + aoff + 16,         Ahg + (long long)(m0 + ar) * lda + k0 + ak + 8);
        CP16(sb + STG_B + aoff,      Bhg + (long long)(n0 + ar) * ldb + k0 + ak);
        CP16(sb + STG_B + aoff + 16, Bhg + (long long)(n0 + ar) * ldb + k0 + ak + 8);
        CP_COMMIT();
    };

    issue(0);

    for (int c = 0; c < nchunks; c++) {
        CP_WAIT(0);
        __syncthreads();
        if (c + 1 < nchunks) issue(c + 1);

        const uint32_t sb = smb + (c & 1) * SMEM_STAGE1;
        const uint32_t AhB = sb, BhB = sb + STG_B;

#pragma unroll
        for (int ks = 0; ks < 2; ks++) {
            uint32_t aH[4][4], bHf[4][2];
            const int kc = ks * 16 + (lane >> 4) * 8;
#pragma unroll
            for (int m = 0; m < 4; m++) {
                const uint32_t off =
                    (uint32_t)((wy * 64 + m * 16 + (lane & 15)) * SKP + kc) * 2u;
                LDSM_X4(aH[m], AhB + off);
            }
            const int kcb = ks * 16 + ((lane >> 3) & 1) * 8;
#pragma unroll
            for (int n = 0; n < 4; n++) {
                const uint32_t off =
                    (uint32_t)((wx * 32 + n * 8 + (lane & 7)) * SKP + kcb) * 2u;
                LDSM_X2(bHf[n], BhB + off);
            }
#pragma unroll
            for (int m = 0; m < 4; m++)
#pragma unroll
                for (int n = 0; n < 4; n++)
                    mma_f16(acc[m][n], aH[m], bHf[n]);
        }
    }

#pragma unroll
    for (int m = 0; m < 4; m++) {
        const int row = m0 + wy * 64 + m * 16 + (lane >> 2);
#pragma unroll
        for (int n = 0; n < 4; n++) {
            const int col = n0 + wx * 32 + n * 8 + (lane & 3) * 2;
            float2 v0, v1;
            v0.x = acc[m][n][0]; v0.y = acc[m][n][1];
            v1.x = acc[m][n][2]; v1.y = acc[m][n][3];
            *(float2*)(C + (long long)row * ldc + col)       = v0;
            *(float2*)(C + (long long)(row + 8) * ldc + col) = v1;
        }
    }
}

// ---------------------------------------------------------------------------
// 2-MMA GEMM (NT): C = A_h @ (B_h + B_l)^T (+bias)   (proj)
// ---------------------------------------------------------------------------
__global__ __launch_bounds__(256) void gemm_tc(
    const __half* __restrict__ Ahg,
    const __half* __restrict__ Bhg, const __half* __restrict__ Blg,
    float* __restrict__ C, const float* __restrict__ bias,
    int K, int lda, int ldb, int ldc)
{
    extern __shared__ __half sm[];
    const uint32_t smb = smem_u32(sm);
    const int tid  = threadIdx.x;
    const int lane = tid & 31;
    const int wrp  = tid >> 5;
    const int wy   = wrp >> 2;
    const int wx   = wrp & 3;

    const int m0 = blockIdx.y * BM;
    const int n0 = blockIdx.x * BN;

    float acc[4][4][4];
#pragma unroll
    for (int m = 0; m < 4; m++)
#pragma unroll
        for (int n = 0; n < 4; n++)
#pragma unroll
            for (int i = 0; i < 4; i++) acc[m][n][i] = 0.f;

    const int nchunks = K >> 5;
    const int ar = tid >> 1;
    const int ak = (tid & 1) * 16;

    auto issue = [&](int c) {
        const int s = c & 1;
        const int k0 = c << 5;
        const uint32_t sb = smb + s * SMEM_STAGE;
        const uint32_t aoff = (uint32_t)(ar * SKP + ak) * 2u;
        CP16(sb + aoff,                  Ahg + (long long)(m0 + ar) * lda + k0 + ak);
        CP16(sb + aoff + 16,             Ahg + (long long)(m0 + ar) * lda + k0 + ak + 8);
        CP16(sb + STG_B + aoff,          Bhg + (long long)(n0 + ar) * ldb + k0 + ak);
        CP16(sb + STG_B + aoff + 16,     Bhg + (long long)(n0 + ar) * ldb + k0 + ak + 8);
        CP16(sb + 2 * STG_B + aoff,      Blg + (long long)(n0 + ar) * ldb + k0 + ak);
        CP16(sb + 2 * STG_B + aoff + 16, Blg + (long long)(n0 + ar) * ldb + k0 + ak + 8);
        CP_COMMIT();
    };

    issue(0);

    for (int c = 0; c < nchunks; c++) {
        CP_WAIT(0);
        __syncthreads();
        if (c + 1 < nchunks) issue(c + 1);

        const uint32_t sb = smb + (c & 1) * SMEM_STAGE;
        const uint32_t AhB = sb;
        const uint32_t BhB = sb + STG_B, BlB = sb + 2 * STG_B;

#pragma unroll
        for (int ks = 0; ks < 2; ks++) {
            uint32_t aH[4][4], bHf[4][2], bLf[4][2];
            const int kc = ks * 16 + (lane >> 4) * 8;
#pragma unroll
            for (int m = 0; m < 4; m++) {
                const uint32_t off =
                    (uint32_t)((wy * 64 + m * 16 + (lane & 15)) * SKP + kc) * 2u;
                LDSM_X4(aH[m], AhB + off);
            }
            const int kcb = ks * 16 + ((lane >> 3) & 1) * 8;
#pragma unroll
            for (int n = 0; n < 4; n++) {
                const uint32_t off =
                    (uint32_t)((wx * 32 + n * 8 + (lane & 7)) * SKP + kcb) * 2u;
                LDSM_X2(bHf[n], BhB + off);
                LDSM_X2(bLf[n], BlB + off);
            }
#pragma unroll
            for (int m = 0; m < 4; m++)
#pragma unroll
                for (int n = 0; n < 4; n++) {
                    mma_f16(acc[m][n], aH[m], bHf[n]);
                    mma_f16(acc[m][n], aH[m], bLf[n]);
                }
        }
    }

#pragma unroll
    for (int m = 0; m < 4; m++) {
        const int row = m0 + wy * 64 + m * 16 + (lane >> 2);
#pragma unroll
        for (int n = 0; n < 4; n++) {
            const int col = n0 + wx * 32 + n * 8 + (lane & 3) * 2;
            float2 v0, v1;
            v0.x = acc[m][n][0]; v0.y = acc[m][n][1];
            v1.x = acc[m][n][2]; v1.y = acc[m][n][3];
            if (bias) {
                float2 bb = *(const float2*)(bias + col);
                v0.x += bb.x; v0.y += bb.y;
                v1.x += bb.x; v1.y += bb.y;
            }
            *(float2*)(C + (long long)row * ldc + col)       = v0;
            *(float2*)(C + (long long)(row + 8) * ldc + col) = v1;
        }
    }
}

// ---------------------------------------------------------------------------
// Fused flash attention: KV chunk 32, 2 CTAs/SM
// ---------------------------------------------------------------------------
__global__ __launch_bounds__(256, 2) void flash_attn()
{
    extern __shared__ char smc[];
    const uint32_t smb = smem_u32(smc);
    const int tid = threadIdx.x, lane = tid & 31, w = tid >> 5;
    const int m0 = blockIdx.x * 128;
    const int bh = blockIdx.y;
    const long long hb = (long long)bh * LL * DD;
    const __half *qhp = g_qh + hb;
    const __half *khp = g_kh + hb, *klp = g_kl + hb;
    const __half *vhp = g_vh + hb, *vlp = g_vl + hb;

#pragma unroll
    for (int i = 0; i < 8; i++) {
        int idx = tid + i * 256;
        int row = idx >> 4, seg = idx & 15;
        CP16(smb + (uint32_t)row * 272u + seg * 16,
             qhp + (long long)(m0 + row) * DD + seg * 8);
    }
    auto stage_kv = [&](int c) {
        const uint32_t base = smb + SM_S0 + (uint32_t)(c & 1) * FSTAGE;
#pragma unroll
        for (int i = 0; i < 8; i++) {
            int idx = tid + i * 256;
            int mat = (idx >> 9) & 3, row = (idx >> 4) & 31, seg = idx & 15;
            const __half* sp = (mat == 0) ? khp : (mat == 1) ? klp
                             : (mat == 2) ? vhp : vlp;
            CP16(base + (uint32_t)mat * KVB + (uint32_t)row * 272u + seg * 16,
                 sp + (long long)(c * 32 + row) * DD + seg * 8);
        }
        CP_COMMIT();
    };
    stage_kv(0);

    float Oacc[16][4];
#pragma unroll
    for (int n = 0; n < 16; n++)
#pragma unroll
        for (int i = 0; i < 4; i++) Oacc[n][i] = 0.f;
    float mr0 = -1e30f, mr1 = -1e30f, lr0 = 0.f, lr1 = 0.f;

    for (int c = 0; c < 64; c++) {
        CP_WAIT(0);
        __syncthreads();
        if (c + 1 < 64) stage_kv(c + 1);

        const uint32_t stg = smb + SM_S0 + (uint32_t)(c & 1) * FSTAGE;
        const uint32_t Kh = stg, Kl = stg + KVB, Vh = stg + 2 * KVB, Vl = stg + 3 * KVB;

        float sacc[4][4];
#pragma unroll
        for (int n = 0; n < 4; n++)
#pragma unroll
            for (int i = 0; i < 4; i++) sacc[n][i] = 0.f;

#pragma unroll
        for (int kd = 0; kd < 8; kd++) {
            uint32_t qf[4];
            const uint32_t qoff =
                ((uint32_t)(w * 16 + (lane & 15)) * 136u + kd * 16 + (lane >> 4) * 8) * 2u;
            LDSM_X4(qf, smb + qoff);

            uint32_t bh4[4][2], bl4[4][2];
            const uint32_t kcb = kd * 16 + ((lane >> 3) & 1) * 8;
#pragma unroll
            for (int nf = 0; nf < 4; nf++) {
                const uint32_t off = ((uint32_t)(nf * 8 + (lane & 7)) * 136u + kcb) * 2u;
                LDSM_X2(bh4[nf], Kh + off);
                LDSM_X2(bl4[nf], Kl + off);
            }
#pragma unroll
            for (int nf = 0; nf < 4; nf++) {
                mma_f16(sacc[nf], qf, bh4[nf]);
                mma_f16(sacc[nf], qf, bl4[nf]);
            }
        }

        float cm0 = -1e30f, cm1 = -1e30f;
#pragma unroll
        for (int nf = 0; nf < 4; nf++) {
            cm0 = fmaxf(cm0, fmaxf(sacc[nf][0], sacc[nf][1]));
            cm1 = fmaxf(cm1, fmaxf(sacc[nf][2], sacc[nf][3]));
        }
        cm0 = fmaxf(cm0, __shfl_xor_sync(0xffffffffu, cm0, 1));
        cm0 = fmaxf(cm0, __shfl_xor_sync(0xffffffffu, cm0, 2));
        cm1 = fmaxf(cm1, __shfl_xor_sync(0xffffffffu, cm1, 1));
        cm1 = fmaxf(cm1, __shfl_xor_sync(0xffffffffu, cm1, 2));
        const float mn0 = fmaxf(mr0, cm0), mn1 = fmaxf(mr1, cm1);
        const float a0 = __expf(mr0 - mn0), a1 = __expf(mr1 - mn1);
        mr0 = mn0; mr1 = mn1;

        float s0 = 0.f, s1 = 0.f;
#pragma unroll
        for (int nf = 0; nf < 4; nf++) {
            sacc[nf][0] = __expf(sacc[nf][0] - mn0);
            sacc[nf][1] = __expf(sacc[nf][1] - mn0);
            sacc[nf][2] = __expf(sacc[nf][2] - mn1);
            sacc[nf][3] = __expf(sacc[nf][3] - mn1);
            s0 += sacc[nf][0] + sacc[nf][1];
            s1 += sacc[nf][2] + sacc[nf][3];
        }
        s0 += __shfl_xor_sync(0xffffffffu, s0, 1);
        s0 += __shfl_xor_sync(0xffffffffu, s0, 2);
        s1 += __shfl_xor_sync(0xffffffffu, s1, 1);
        s1 += __shfl_xor_sync(0xffffffffu, s1, 2);
        lr0 = lr0 * a0 + s0;
        lr1 = lr1 * a1 + s1;

#pragma unroll
        for (int n = 0; n < 16; n++) {
            Oacc[n][0] *= a0; Oacc[n][1] *= a0;
            Oacc[n][2] *= a1; Oacc[n][3] *= a1;
        }

        uint32_t ph[2][4];
#pragma unroll
        for (int kv = 0; kv < 2; kv++) {
            cvt2h(sacc[2 * kv][0],     sacc[2 * kv][1],     ph[kv][0]);
            cvt2h(sacc[2 * kv][2],     sacc[2 * kv][3],     ph[kv][1]);
            cvt2h(sacc[2 * kv + 1][0], sacc[2 * kv + 1][1], ph[kv][2]);
            cvt2h(sacc[2 * kv + 1][2], sacc[2 * kv + 1][3], ph[kv][3]);
        }

#pragma unroll
        for (int kv = 0; kv < 2; kv++) {
            const uint32_t vrow = (uint32_t)(kv * 16 + (lane & 15));
#pragma unroll
            for (int nfp = 0; nfp < 8; nfp++) {
                const uint32_t voff =
                    (vrow * 136u + (uint32_t)(nfp * 16 + ((lane >> 4) & 1) * 8)) * 2u;
                uint32_t vbh[4], vbl[4];
                LDSM_X4T(vbh, Vh + voff);
                LDSM_X4T(vbl, Vl + voff);
                mma_f16(Oacc[2 * nfp],     ph[kv], vbh);
                mma_f16(Oacc[2 * nfp],     ph[kv], vbl);
                mma_f16(Oacc[2 * nfp + 1], ph[kv], vbh + 2);
                mma_f16(Oacc[2 * nfp + 1], ph[kv], vbl + 2);
            }
        }
    }

    const float inv0 = 1.f / lr0, inv1 = 1.f / lr1;
    const int b = bh >> 4, h = bh & 15;
    const int r0 = m0 + w * 16 + (lane >> 2);
    const long long base0 = (long long)(b * LL + r0) * DIMM + h * DD;
    const long long base1 = base0 + 8LL * DIMM;
#pragma unroll
    for (int nf = 0; nf < 16; nf++) {
        const int col = nf * 8 + (lane & 3) * 2;
        uint32_t hh;
        cvt2h(Oacc[nf][0] * inv0, Oacc[nf][1] * inv0, hh);
        *(uint32_t*)(g_oh + base0 + col) = hh;
        cvt2h(Oacc[nf][2] * inv1, Oacc[nf][3] * inv1, hh);
        *(uint32_t*)(g_oh + base1 + col) = hh;
    }
}

// ---------------------------------------------------------------------------
// Prep: RMSNorm + RoPE (+attn scale on q) -> fp16 q(hi), k(hi/lo), v(hi/lo)
// ---------------------------------------------------------------------------
__global__ __launch_bounds__(256) void prep_kernel(
    const float* __restrict__ qkv, const float* __restrict__ pe,
    const float* __restrict__ qsc, const float* __restrict__ ksc)
{
    const int warp = (blockIdx.x * blockDim.x + threadIdx.x) >> 5;
    const int lane = threadIdx.x & 31;
    const int b = warp >> 15;
    const int rem = warp & 32767;
    const int h = rem >> 11;
    const int l = rem & 2047;

    const long long src = ((long long)(b * LL + l)) * E3 + h * DD + lane * 4;
    float4 qv = *(const float4*)(qkv + src);
    float4 kv = *(const float4*)(qkv + src + DIMM);
    float4 vv = *(const float4*)(qkv + src + 2 * DIMM);

    float sq = qv.x * qv.x + qv.y * qv.y + qv.z * qv.z + qv.w * qv.w;
#pragma unroll
    for (int o = 16; o; o >>= 1) sq += __shfl_xor_sync(0xffffffffu, sq, o);
    float rq = rsqrtf(sq * (1.0f / 128.0f) + 1e-6f);
    float4 qs4 = *(const float4*)(qsc + lane * 4);
    qv.x *= rq * qs4.x; qv.y *= rq * qs4.y; qv.z *= rq * qs4.z; qv.w *= rq * qs4.w;

    float sk = kv.x * kv.x + kv.y * kv.y + kv.z * kv.z + kv.w * kv.w;
#pragma unroll
    for (int o = 16; o; o >>= 1) sk += __shfl_xor_sync(0xffffffffu, sk, o);
    float rk = rsqrtf(sk * (1.0f / 128.0f) + 1e-6f);
    float4 ks4 = *(const float4*)(ksc + lane * 4);
    kv.x *= rk * ks4.x; kv.y *= rk * ks4.y; kv.z *= rk * ks4.z; kv.w *= rk * ks4.w;

    const float* peb = pe + (long long)l * 256 + lane * 8;
    float a00 = peb[0], a01 = peb[1], a10 = peb[2], a11 = peb[3];
    float b00 = peb[4], b01 = peb[5], b10 = peb[6], b11 = peb[7];

    const float asc = 0.08838834764831845f;
    float4 qo, ko;
    qo.x = (a00 * qv.x + a01 * qv.y) * asc;  qo.y = (a10 * qv.x + a11 * qv.y) * asc;
    qo.z = (b00 * qv.z + b01 * qv.w) * asc;  qo.w = (b10 * qv.z + b11 * qv.w) * asc;
    ko.x = a00 * kv.x + a01 * kv.y;  ko.y = a10 * kv.x + a11 * kv.y;
    ko.z = b00 * kv.z + b01 * kv.w;  ko.w = b10 * kv.z + b11 * kv.w;

    const long long dst = (long long)warp * DD + lane * 4;
    uint2 hv, lv;
    cvt2h(qo.x, qo.y, hv.x); cvt2h(qo.z, qo.w, hv.y);
    *(uint2*)(g_qh + dst) = hv;
    split2h(ko.x, ko.y, hv.x, lv.x); split2h(ko.z, ko.w, hv.y, lv.y);
    *(uint2*)(g_kh + dst) = hv; *(uint2*)(g_kl + dst) = lv;
    split2h(vv.x, vv.y, hv.x, lv.x); split2h(vv.z, vv.w, hv.y, lv.y);
    *(uint2*)(g_vh + dst) = hv; *(uint2*)(g_vl + dst) = lv;
}

// ---------------------------------------------------------------------------
// Launch
// ---------------------------------------------------------------------------
extern "C" void kernel_launch(void* const* d_in, const int* in_sizes, int n_in,
                              void* d_out, int out_size)
{
    const float* x      = (const float*)d_in[0];
    const float* pe     = (const float*)d_in[1];
    const float* qkv_w  = (const float*)d_in[2];
    const float* q_sc   = (const float*)d_in[3];
    const float* k_sc   = (const float*)d_in[4];
    const float* proj_w = (const float*)d_in[5];
    const float* proj_b = (const float*)d_in[6];
    float* out = (float*)d_out;

    float* qkv;
    __half *xh, *wqh, *wph, *wpl, *oh;
    cudaGetSymbolAddress((void**)&qkv, g_qkv);
    cudaGetSymbolAddress((void**)&xh,  g_xh);
    cudaGetSymbolAddress((void**)&wqh, g_wqh);
    cudaGetSymbolAddress((void**)&wph, g_wph); cudaGetSymbolAddress((void**)&wpl, g_wpl);
    cudaGetSymbolAddress((void**)&oh,  g_oh);

    cudaFuncSetAttribute(gemm_tc1, cudaFuncAttributeMaxDynamicSharedMemorySize, SMEM_TOTAL1);
    cudaFuncSetAttribute(gemm_tc, cudaFuncAttributeMaxDynamicSharedMemorySize, SMEM_TOTAL);
    cudaFuncSetAttribute(flash_attn, cudaFuncAttributeMaxDynamicSharedMemorySize, FSMEM);

    // 0) one fused conversion launch
    convert_all<<<(N4_X + N4_WQ + N4_WP + 255) / 256, 256>>>(x, qkv_w, proj_w);

    // 1) QKV: 1-MMA, 2-stage
    gemm_tc1<<<dim3(E3 / BN, MROWS / BM, 1), 256, SMEM_TOTAL1>>>(
        xh, wqh, qkv, DIMM, DIMM, DIMM, E3);

    // 2) RMSNorm + RoPE
    prep_kernel<<<(BH * LL) / 8, 256>>>(qkv, pe, q_sc, k_sc);

    // 3) flash attention
    flash_attn<<<dim3(LL / 128, BH, 1), 256, FSMEM>>>();

    // 4) proj: 2-MMA, 2-stage
    gemm_tc<<<dim3(DIMM / BN, MROWS / BM, 1), 256, SMEM_TOTAL>>>(
        oh, wph, wpl, out, proj_b, DIMM, DIMM, DIMM, DIMM);
}